// round 2
// baseline (speedup 1.0000x reference)
#include <cuda_runtime.h>
#include <math.h>

#define D_MODEL 1024
#define D_FF    4096
#define HEADS   16
#define HD      64
#define BB      2
#define SS      2048
#define MTOK    (BB*SS)      /* 4096 rows */
#define BH      (BB*HEADS)   /* 32 */

// ---------------------------------------------------------------------------
// Scratch (device globals; allocations are forbidden)
// ---------------------------------------------------------------------------
__device__ __align__(16) float g_q   [MTOK*(size_t)D_MODEL];
__device__ __align__(16) float g_k   [MTOK*(size_t)D_MODEL];
__device__ __align__(16) float g_v   [MTOK*(size_t)D_MODEL];
__device__ __align__(16) float g_attn[MTOK*(size_t)D_MODEL];
__device__ __align__(16) float g_h   [MTOK*(size_t)D_MODEL];
__device__ __align__(16) float g_y1  [MTOK*(size_t)D_MODEL];
__device__ __align__(16) float g_y2  [MTOK*(size_t)D_MODEL];
__device__ __align__(16) float g_ff  [MTOK*(size_t)D_FF];

// ---------------------------------------------------------------------------
// SGEMM: C[M,N] = A[M,K] @ W[K,N] + bias (optional ReLU).
// 128x128 block tile, BK=16, 8x8 per-thread microtile, 256 threads.
// All dims are multiples of the tile sizes here -> no bounds checks.
// ---------------------------------------------------------------------------
#define GBM 128
#define GBN 128
#define GBK 16

__global__ __launch_bounds__(256)
void sgemm_bias_kernel(const float* __restrict__ A, const float* __restrict__ W,
                       const float* __restrict__ bias, float* __restrict__ C,
                       int M, int N, int K, int relu)
{
    __shared__ float As[GBK][GBM + 1];   // transposed A tile
    __shared__ float Bs[GBK][GBN + 4];

    const int tid = threadIdx.x;
    const int tx  = tid & 15;
    const int ty  = tid >> 4;
    const int row0 = blockIdx.y * GBM;
    const int col0 = blockIdx.x * GBN;

    float acc[8][8];
#pragma unroll
    for (int i = 0; i < 8; i++)
#pragma unroll
        for (int j = 0; j < 8; j++) acc[i][j] = 0.f;

    const int a_r = tid >> 2;           // 0..63
    const int a_c = (tid & 3) * 4;      // 0,4,8,12
    const int b_r = tid >> 5;           // 0..7
    const int b_c = (tid & 31) * 4;     // 0..124

    for (int k0 = 0; k0 < K; k0 += GBK) {
#pragma unroll
        for (int u = 0; u < 2; u++) {
            int r = a_r + u * 64;
            float4 t = *(const float4*)(A + (size_t)(row0 + r) * K + k0 + a_c);
            As[a_c + 0][r] = t.x;
            As[a_c + 1][r] = t.y;
            As[a_c + 2][r] = t.z;
            As[a_c + 3][r] = t.w;
        }
#pragma unroll
        for (int u = 0; u < 2; u++) {
            int r = b_r + u * 8;
            float4 t = *(const float4*)(W + (size_t)(k0 + r) * N + col0 + b_c);
            *(float4*)&Bs[r][b_c] = t;
        }
        __syncthreads();

#pragma unroll
        for (int k = 0; k < GBK; k++) {
            float ra[8], rb[8];
#pragma unroll
            for (int i = 0; i < 8; i++) ra[i] = As[k][ty * 8 + i];
#pragma unroll
            for (int j = 0; j < 8; j++) rb[j] = Bs[k][tx * 8 + j];
#pragma unroll
            for (int i = 0; i < 8; i++)
#pragma unroll
                for (int j = 0; j < 8; j++)
                    acc[i][j] = fmaf(ra[i], rb[j], acc[i][j]);
        }
        __syncthreads();
    }

#pragma unroll
    for (int i = 0; i < 8; i++) {
        int r = row0 + ty * 8 + i;
#pragma unroll
        for (int j = 0; j < 8; j += 4) {
            int c = col0 + tx * 8 + j;
            float4 o;
            o.x = acc[i][j + 0] + bias[c + 0];
            o.y = acc[i][j + 1] + bias[c + 1];
            o.z = acc[i][j + 2] + bias[c + 2];
            o.w = acc[i][j + 3] + bias[c + 3];
            if (relu) {
                o.x = fmaxf(o.x, 0.f); o.y = fmaxf(o.y, 0.f);
                o.z = fmaxf(o.z, 0.f); o.w = fmaxf(o.w, 0.f);
            }
            *(float4*)(C + (size_t)r * N + c) = o;
        }
    }
}

// ---------------------------------------------------------------------------
// Streaming-softmax attention, fp32, reading the projection outputs DIRECTLY
// with the reference's no-transpose reshape folded into the address math:
//   head h, seq s'  ->  src row (b*SS + 128*h + s'/16), cols [64*(s'%16), +64)
// Output is written straight into merged-heads layout Y[b][s'][h*64+c]
// (== transpose(0,2,1,3).reshape in the reference).
// Block: 64 query rows, 256 threads (tx=col 0..15, ty=row 0..15), KV tiles 32.
// ---------------------------------------------------------------------------
#define AT_BM 64
#define AT_BN 32
#define NEG_BIG (-1e30f)

__device__ __forceinline__ size_t head_src_off(int b, int h, int s)
{
    return ((size_t)(b * SS + 128 * h + (s >> 4))) * D_MODEL
         + (size_t)(s & 15) * HD;
}

__global__ __launch_bounds__(256)
void attn_kernel(const float* __restrict__ Q, const float* __restrict__ K,
                 const float* __restrict__ V, float* __restrict__ Y, int causal)
{
    __shared__ float Qs[AT_BM][HD + 1];
    __shared__ float Ks[AT_BN][HD + 1];
    __shared__ float Vs[AT_BN][HD + 1];
    __shared__ float Ps[AT_BM][AT_BN];

    const int tid = threadIdx.x;
    const int tx = tid & 15;
    const int ty = tid >> 4;
    const int bh = blockIdx.y;
    const int h  = bh & (HEADS - 1);
    const int b  = bh >> 4;
    const int q0 = blockIdx.x * AT_BM;

    // Load Q tile (float4 per thread iter; 64 rows * 16 float4-cols)
    for (int i = tid; i < AT_BM * 16; i += 256) {
        int r = i >> 4, d4 = (i & 15);
        float4 t = ((const float4*)(Q + head_src_off(b, h, q0 + r)))[d4];
        Qs[r][d4 * 4 + 0] = t.x; Qs[r][d4 * 4 + 1] = t.y;
        Qs[r][d4 * 4 + 2] = t.z; Qs[r][d4 * 4 + 3] = t.w;
    }

    float m[4], l[4], o[4][4];
#pragma unroll
    for (int i = 0; i < 4; i++) {
        m[i] = NEG_BIG; l[i] = 0.f;
#pragma unroll
        for (int j = 0; j < 4; j++) o[i][j] = 0.f;
    }

    const int ntiles = causal ? (q0 / AT_BN + AT_BM / AT_BN) : (SS / AT_BN);
    for (int t = 0; t < ntiles; t++) {
        const int kv0 = t * AT_BN;
        __syncthreads();
        for (int i = tid; i < AT_BN * 16; i += 256) {
            int r = i >> 4, d4 = (i & 15);
            size_t so = head_src_off(b, h, kv0 + r);
            float4 tk = ((const float4*)(K + so))[d4];
            float4 tv = ((const float4*)(V + so))[d4];
            Ks[r][d4 * 4 + 0] = tk.x; Ks[r][d4 * 4 + 1] = tk.y;
            Ks[r][d4 * 4 + 2] = tk.z; Ks[r][d4 * 4 + 3] = tk.w;
            Vs[r][d4 * 4 + 0] = tv.x; Vs[r][d4 * 4 + 1] = tv.y;
            Vs[r][d4 * 4 + 2] = tv.z; Vs[r][d4 * 4 + 3] = tv.w;
        }
        __syncthreads();

        // S = Q K^T  (rows ty*4+i, cols tx + 16*j)
        float sv[4][2];
#pragma unroll
        for (int i = 0; i < 4; i++) { sv[i][0] = 0.f; sv[i][1] = 0.f; }
#pragma unroll 8
        for (int d = 0; d < HD; d++) {
            float k0v = Ks[tx][d];
            float k1v = Ks[tx + 16][d];
#pragma unroll
            for (int i = 0; i < 4; i++) {
                float qv = Qs[ty * 4 + i][d];
                sv[i][0] = fmaf(qv, k0v, sv[i][0]);
                sv[i][1] = fmaf(qv, k1v, sv[i][1]);
            }
        }

#pragma unroll
        for (int i = 0; i < 4; i++) {
            const int qg = q0 + ty * 4 + i;
#pragma unroll
            for (int j = 0; j < 2; j++) {
                int kg = kv0 + tx + j * 16;
                float s = sv[i][j] * 0.125f;          // 1/sqrt(64)
                if (causal && kg > qg) s = NEG_BIG;
                sv[i][j] = s;
            }
            float rmax = fmaxf(sv[i][0], sv[i][1]);
#pragma unroll
            for (int off = 8; off > 0; off >>= 1)
                rmax = fmaxf(rmax, __shfl_xor_sync(0xffffffffu, rmax, off));
            float mnew = fmaxf(m[i], rmax);
            float sc = __expf(m[i] - mnew);
            float p0 = __expf(sv[i][0] - mnew);
            float p1 = __expf(sv[i][1] - mnew);
            float rsum = p0 + p1;
#pragma unroll
            for (int off = 8; off > 0; off >>= 1)
                rsum += __shfl_xor_sync(0xffffffffu, rsum, off);
            l[i] = l[i] * sc + rsum;
            m[i] = mnew;
#pragma unroll
            for (int j = 0; j < 4; j++) o[i][j] *= sc;
            Ps[ty * 4 + i][tx]      = p0;
            Ps[ty * 4 + i][tx + 16] = p1;
        }
        __syncthreads();

        // O += P @ V   (cols tx + 16*j, j = 0..3)
#pragma unroll 4
        for (int kk = 0; kk < AT_BN; kk++) {
            float vb[4];
#pragma unroll
            for (int j = 0; j < 4; j++) vb[j] = Vs[kk][tx + j * 16];
#pragma unroll
            for (int i = 0; i < 4; i++) {
                float pv = Ps[ty * 4 + i][kk];
#pragma unroll
                for (int j = 0; j < 4; j++)
                    o[i][j] = fmaf(pv, vb[j], o[i][j]);
            }
        }
    }

    // write merged-heads: Y[b][q][h*64 + c]
    float* Yp = Y + (size_t)b * SS * D_MODEL + (size_t)h * HD;
#pragma unroll
    for (int i = 0; i < 4; i++) {
        float inv = 1.f / l[i];
        size_t rb = (size_t)(q0 + ty * 4 + i) * D_MODEL;
#pragma unroll
        for (int j = 0; j < 4; j++)
            Yp[rb + tx + j * 16] = o[i][j] * inv;
    }
}

// ---------------------------------------------------------------------------
// Fused residual-add + LayerNorm over last dim (1024). One CTA per row.
// ---------------------------------------------------------------------------
__global__ __launch_bounds__(256)
void add_ln_kernel(const float* __restrict__ X, const float* __restrict__ Hh,
                   const float* __restrict__ g, const float* __restrict__ be,
                   float* __restrict__ Yo)
{
    const int row = blockIdx.x;
    const size_t base = (size_t)row * D_MODEL;
    const int tid = threadIdx.x;

    float v[4];
    float s = 0.f, s2 = 0.f;
#pragma unroll
    for (int u = 0; u < 4; u++) {
        int c = tid + u * 256;
        float t = X[base + c] + Hh[base + c];
        v[u] = t; s += t; s2 += t * t;
    }
#pragma unroll
    for (int off = 16; off > 0; off >>= 1) {
        s  += __shfl_down_sync(0xffffffffu, s,  off);
        s2 += __shfl_down_sync(0xffffffffu, s2, off);
    }
    __shared__ float rs_[8], rs2_[8];
    if ((tid & 31) == 0) { rs_[tid >> 5] = s; rs2_[tid >> 5] = s2; }
    __syncthreads();
    float ts = 0.f, ts2 = 0.f;
#pragma unroll
    for (int w = 0; w < 8; w++) { ts += rs_[w]; ts2 += rs2_[w]; }

    float mu   = ts * (1.0f / D_MODEL);
    float var  = ts2 * (1.0f / D_MODEL) - mu * mu;
    float rstd = rsqrtf(var + 1e-5f);
#pragma unroll
    for (int u = 0; u < 4; u++) {
        int c = tid + u * 256;
        Yo[base + c] = (v[u] - mu) * rstd * g[c] + be[c];
    }
}

// ---------------------------------------------------------------------------
// kernel_launch
// ---------------------------------------------------------------------------
extern "C" void kernel_launch(void* const* d_in, const int* in_sizes, int n_in,
                              void* d_out, int out_size)
{
    (void)in_sizes; (void)n_in; (void)out_size;

    const float* x    = (const float*)d_in[0];
    const float* enc  = (const float*)d_in[1];
    const float* s_wq = (const float*)d_in[2];  const float* s_bq = (const float*)d_in[3];
    const float* s_wk = (const float*)d_in[4];  const float* s_bk = (const float*)d_in[5];
    const float* s_wv = (const float*)d_in[6];  const float* s_bv = (const float*)d_in[7];
    const float* s_wo = (const float*)d_in[8];  const float* s_bo = (const float*)d_in[9];
    const float* c_wq = (const float*)d_in[10]; const float* c_bq = (const float*)d_in[11];
    const float* c_wk = (const float*)d_in[12]; const float* c_bk = (const float*)d_in[13];
    const float* c_wv = (const float*)d_in[14]; const float* c_bv = (const float*)d_in[15];
    const float* c_wo = (const float*)d_in[16]; const float* c_bo = (const float*)d_in[17];
    const float* f_w1 = (const float*)d_in[18]; const float* f_b1 = (const float*)d_in[19];
    const float* f_w2 = (const float*)d_in[20]; const float* f_b2 = (const float*)d_in[21];
    const float* ln1g = (const float*)d_in[22]; const float* ln1b = (const float*)d_in[23];
    const float* ln2g = (const float*)d_in[24]; const float* ln2b = (const float*)d_in[25];
    const float* ln3g = (const float*)d_in[26]; const float* ln3b = (const float*)d_in[27];
    float* out = (float*)d_out;

    float *q, *k, *v, *attn, *hb, *y1, *y2, *ff;
    cudaGetSymbolAddress((void**)&q,    g_q);
    cudaGetSymbolAddress((void**)&k,    g_k);
    cudaGetSymbolAddress((void**)&v,    g_v);
    cudaGetSymbolAddress((void**)&attn, g_attn);
    cudaGetSymbolAddress((void**)&hb,   g_h);
    cudaGetSymbolAddress((void**)&y1,   g_y1);
    cudaGetSymbolAddress((void**)&y2,   g_y2);
    cudaGetSymbolAddress((void**)&ff,   g_ff);

    const dim3 thr(256);
    const dim3 gN1024(D_MODEL / GBN, MTOK / GBM);   // (8, 32)
    const dim3 gN4096(D_FF   / GBN, MTOK / GBM);    // (32, 32)
    const dim3 gAttn(SS / AT_BM, BH);               // (32, 32)
    const dim3 gLN(MTOK);                           // 4096

    // ---- masked self-attention ----
    sgemm_bias_kernel<<<gN1024, thr>>>(x, s_wq, s_bq, q, MTOK, D_MODEL, D_MODEL, 0);
    sgemm_bias_kernel<<<gN1024, thr>>>(x, s_wk, s_bk, k, MTOK, D_MODEL, D_MODEL, 0);
    sgemm_bias_kernel<<<gN1024, thr>>>(x, s_wv, s_bv, v, MTOK, D_MODEL, D_MODEL, 0);
    attn_kernel<<<gAttn, thr>>>(q, k, v, attn, 1);
    sgemm_bias_kernel<<<gN1024, thr>>>(attn, s_wo, s_bo, hb, MTOK, D_MODEL, D_MODEL, 0);
    add_ln_kernel<<<gLN, thr>>>(x, hb, ln1g, ln1b, y1);

    // ---- cross-attention ----
    sgemm_bias_kernel<<<gN1024, thr>>>(y1,  c_wq, c_bq, q, MTOK, D_MODEL, D_MODEL, 0);
    sgemm_bias_kernel<<<gN1024, thr>>>(enc, c_wk, c_bk, k, MTOK, D_MODEL, D_MODEL, 0);
    sgemm_bias_kernel<<<gN1024, thr>>>(enc, c_wv, c_bv, v, MTOK, D_MODEL, D_MODEL, 0);
    attn_kernel<<<gAttn, thr>>>(q, k, v, attn, 0);
    sgemm_bias_kernel<<<gN1024, thr>>>(attn, c_wo, c_bo, hb, MTOK, D_MODEL, D_MODEL, 0);
    add_ln_kernel<<<gLN, thr>>>(y1, hb, ln2g, ln2b, y2);

    // ---- FFN ----
    sgemm_bias_kernel<<<gN4096, thr>>>(y2, f_w1, f_b1, ff, MTOK, D_FF, D_MODEL, 1);
    sgemm_bias_kernel<<<gN1024, thr>>>(ff, f_w2, f_b2, hb, MTOK, D_MODEL, D_FF, 0);
    add_ln_kernel<<<gLN, thr>>>(y2, hb, ln3g, ln3b, out);
}

// round 5
// speedup vs baseline: 1.5870x; 1.5870x over previous
#include <cuda_runtime.h>
#include <cuda_bf16.h>
#include <math.h>
#include <stdint.h>

#define D_MODEL 1024
#define D_FF    4096
#define HEADS   16
#define HD      64
#define BB      2
#define SS      2048
#define MTOK    (BB*SS)      /* 4096 rows */
#define BH      (BB*HEADS)   /* 32 */

// ---------------------------------------------------------------------------
// Scratch (device globals; allocations are forbidden)
// ---------------------------------------------------------------------------
__device__ __align__(16) float g_q   [MTOK*(size_t)D_MODEL];
__device__ __align__(16) float g_k   [MTOK*(size_t)D_MODEL];
__device__ __align__(16) float g_v   [MTOK*(size_t)D_MODEL];
__device__ __align__(16) float g_attn[MTOK*(size_t)D_MODEL];
__device__ __align__(16) float g_h   [MTOK*(size_t)D_MODEL];
__device__ __align__(16) float g_y1  [MTOK*(size_t)D_MODEL];
__device__ __align__(16) float g_y2  [MTOK*(size_t)D_MODEL];
__device__ __align__(16) float g_ff  [MTOK*(size_t)D_FF];

// bf16 hi/lo scratch for tensor-core GEMMs
__device__ __align__(16) __nv_bfloat16 g_ah[MTOK*(size_t)D_FF];    // activations hi
__device__ __align__(16) __nv_bfloat16 g_al[MTOK*(size_t)D_FF];    // activations lo
__device__ __align__(16) __nv_bfloat16 g_wh[(size_t)D_FF*D_MODEL]; // weight^T hi  [N][K]
__device__ __align__(16) __nv_bfloat16 g_wl[(size_t)D_FF*D_MODEL]; // weight^T lo  [N][K]

// ---------------------------------------------------------------------------
// fp32 -> bf16 hi/lo split (elementwise), n4 = n/4
// ---------------------------------------------------------------------------
__global__ __launch_bounds__(256)
void split_kernel(const float* __restrict__ in, __nv_bfloat16* __restrict__ hi,
                  __nv_bfloat16* __restrict__ lo, int n4)
{
    int i = blockIdx.x * 256 + threadIdx.x;
    if (i >= n4) return;
    float4 f = ((const float4*)in)[i];
    float fv[4] = {f.x, f.y, f.z, f.w};
#pragma unroll
    for (int c = 0; c < 4; c++) {
        __nv_bfloat16 h = __float2bfloat16(fv[c]);
        __nv_bfloat16 l = __float2bfloat16(fv[c] - __bfloat162float(h));
        hi[(size_t)i * 4 + c] = h;
        lo[(size_t)i * 4 + c] = l;
    }
}

// ---------------------------------------------------------------------------
// W[K][N] fp32 -> Wt_hi/Wt_lo [N][K] bf16 (tiled transpose + split)
// ---------------------------------------------------------------------------
__global__ __launch_bounds__(256)
void splitT_kernel(const float* __restrict__ W, __nv_bfloat16* __restrict__ hi,
                   __nv_bfloat16* __restrict__ lo, int Kd, int Nd)
{
    __shared__ float t[32][33];
    int n0 = blockIdx.x * 32, k0 = blockIdx.y * 32;
    int tx = threadIdx.x & 31, ty = threadIdx.x >> 5;  // ty 0..7
#pragma unroll
    for (int r = ty; r < 32; r += 8)
        t[r][tx] = W[(size_t)(k0 + r) * Nd + n0 + tx];
    __syncthreads();
#pragma unroll
    for (int r = ty; r < 32; r += 8) {
        float f = t[tx][r];                     // = W[k0+tx][n0+r]
        __nv_bfloat16 h = __float2bfloat16(f);
        __nv_bfloat16 l = __float2bfloat16(f - __bfloat162float(h));
        size_t o = (size_t)(n0 + r) * Kd + k0 + tx;
        hi[o] = h; lo[o] = l;
    }
}

// ---------------------------------------------------------------------------
// bf16x3 GEMM via mma.sync (m16n8k16), C = A @ W + bias (opt ReLU)
// A: Ahi/Alo [M][K] bf16; B: Bhi/Blo [N][K] bf16 (pre-transposed).
// CTA 128x128, 8 warps (2m x 4n), warp tile 64x32. BK=32, cp.async dbl-buffer.
// Smem row stride 40 bf16 (80B) -> conflict-free per-lane fragment LDS.
// ---------------------------------------------------------------------------
#define GBK     32
#define SSTRIDE 40                              /* bf16 per smem row */
#define TILEB   (128 * SSTRIDE * 2)             /* 10240 bytes per tile */
#define BUFB    (4 * TILEB)                     /* 4 tiles per stage */
#define GEMM_SMEM (2 * BUFB)                    /* 81920 bytes */

__device__ __forceinline__ void mma16816(float* d, const uint32_t* a, const uint32_t* b)
{
    asm volatile(
        "mma.sync.aligned.m16n8k16.row.col.f32.bf16.bf16.f32 "
        "{%0,%1,%2,%3}, {%4,%5,%6,%7}, {%8,%9}, {%0,%1,%2,%3};"
        : "+f"(d[0]), "+f"(d[1]), "+f"(d[2]), "+f"(d[3])
        : "r"(a[0]), "r"(a[1]), "r"(a[2]), "r"(a[3]), "r"(b[0]), "r"(b[1]));
}

__device__ __forceinline__ void cp16(void* sdst, const void* gsrc)
{
    uint32_t d;
    asm("{ .reg .u64 t; cvta.to.shared.u64 t, %1; cvt.u32.u64 %0, t; }" : "=r"(d) : "l"(sdst));
    asm volatile("cp.async.cg.shared.global [%0], [%1], 16;\n" :: "r"(d), "l"(gsrc));
}

// One stage: copy 4 tiles (Ah, Al, Bh, Bl), each 128 rows x 32 bf16.
__device__ __forceinline__ void load_stage(char* buf,
        const __nv_bfloat16* pAh, const __nv_bfloat16* pAl,
        const __nv_bfloat16* pBh, const __nv_bfloat16* pBl,
        int K, int k0, int tid)
{
    const __nv_bfloat16* srcs[4] = {pAh, pAl, pBh, pBl};
#pragma unroll
    for (int t = 0; t < 4; t++) {
        char* tb = buf + t * TILEB;
        const __nv_bfloat16* g = srcs[t] + k0;
#pragma unroll
        for (int u = 0; u < 2; u++) {
            int id = tid + u * 256;             // 512 chunks of 16B
            int r = id >> 2, c = id & 3;
            cp16(tb + r * (SSTRIDE * 2) + c * 16, g + (size_t)r * K + c * 8);
        }
    }
}

__global__ __launch_bounds__(256)
void gemm_bf16x3(const __nv_bfloat16* __restrict__ Ahi, const __nv_bfloat16* __restrict__ Alo,
                 const __nv_bfloat16* __restrict__ Bhi, const __nv_bfloat16* __restrict__ Blo,
                 const float* __restrict__ bias, float* __restrict__ C,
                 int M, int N, int K, int relu)
{
    extern __shared__ char smem[];

    const int tid = threadIdx.x;
    const int wid = tid >> 5;
    const int lid = tid & 31;
    const int wm  = wid >> 2;                   // 0..1  (64 rows each)
    const int wn  = wid & 3;                    // 0..3  (32 cols each)
    const int m0  = blockIdx.y * 128;
    const int n0  = blockIdx.x * 128;

    const __nv_bfloat16* pAh = Ahi + (size_t)m0 * K;
    const __nv_bfloat16* pAl = Alo + (size_t)m0 * K;
    const __nv_bfloat16* pBh = Bhi + (size_t)n0 * K;
    const __nv_bfloat16* pBl = Blo + (size_t)n0 * K;

    float acc[4][4][4];
#pragma unroll
    for (int i = 0; i < 4; i++)
#pragma unroll
        for (int j = 0; j < 4; j++)
#pragma unroll
            for (int c = 0; c < 4; c++) acc[i][j][c] = 0.f;

    // Per-lane fragment byte offsets within a tile (row-stride 80B).
    const int gr = lid >> 2;                    // 0..7
    const int gt = lid & 3;                     // 0..3
    // A: m-tile mt -> rows wm*64 + mt*16 + gr (+8), k byte gt*4 (+16) (+32 for kstep 1)
    // B: n-tile nt -> rows wn*32 + nt*8  + gr,      k byte gt*4 (+16) (+32 for kstep 1)
    const int aRow0 = wm * 64 + gr;
    const int bRow0 = wn * 32 + gr;

    const int nst = K / GBK;

    load_stage(smem, pAh, pAl, pBh, pBl, K, 0, tid);
    asm volatile("cp.async.commit_group;\n" ::: "memory");

    for (int s = 0; s < nst; s++) {
        if (s + 1 < nst) {
            load_stage(smem + ((s + 1) & 1) * BUFB, pAh, pAl, pBh, pBl,
                       K, (s + 1) * GBK, tid);
            asm volatile("cp.async.commit_group;\n" ::: "memory");
            asm volatile("cp.async.wait_group 1;\n" ::: "memory");
        } else {
            asm volatile("cp.async.wait_group 0;\n" ::: "memory");
        }
        __syncthreads();

        char* buf = smem + (s & 1) * BUFB;
        char* tAh = buf;
        char* tAl = buf + TILEB;
        char* tBh = buf + 2 * TILEB;
        char* tBl = buf + 3 * TILEB;

#pragma unroll
        for (int ks = 0; ks < 2; ks++) {
            const int kb = ks * 32 + gt * 4;    // k byte base for this lane
            uint32_t ah[4][4], al[4][4], bh[4][2], bl[4][2];
#pragma unroll
            for (int mt = 0; mt < 4; mt++) {
                int r0 = (aRow0 + mt * 16) * (SSTRIDE * 2);
                int r8 = r0 + 8 * (SSTRIDE * 2);
                ah[mt][0] = *(uint32_t*)(tAh + r0 + kb);
                ah[mt][1] = *(uint32_t*)(tAh + r8 + kb);
                ah[mt][2] = *(uint32_t*)(tAh + r0 + kb + 16);
                ah[mt][3] = *(uint32_t*)(tAh + r8 + kb + 16);
                al[mt][0] = *(uint32_t*)(tAl + r0 + kb);
                al[mt][1] = *(uint32_t*)(tAl + r8 + kb);
                al[mt][2] = *(uint32_t*)(tAl + r0 + kb + 16);
                al[mt][3] = *(uint32_t*)(tAl + r8 + kb + 16);
            }
#pragma unroll
            for (int nt = 0; nt < 4; nt++) {
                int r = (bRow0 + nt * 8) * (SSTRIDE * 2);
                bh[nt][0] = *(uint32_t*)(tBh + r + kb);
                bh[nt][1] = *(uint32_t*)(tBh + r + kb + 16);
                bl[nt][0] = *(uint32_t*)(tBl + r + kb);
                bl[nt][1] = *(uint32_t*)(tBl + r + kb + 16);
            }
#pragma unroll
            for (int mt = 0; mt < 4; mt++)
#pragma unroll
                for (int nt = 0; nt < 4; nt++) {
                    mma16816(acc[mt][nt], ah[mt], bh[nt]);   // hi*hi
                    mma16816(acc[mt][nt], ah[mt], bl[nt]);   // hi*lo
                    mma16816(acc[mt][nt], al[mt], bh[nt]);   // lo*hi
                }
        }
        __syncthreads();
    }

    // ---- epilogue: bias (+ReLU), direct float2 stores ----
#pragma unroll
    for (int mt = 0; mt < 4; mt++) {
        int row = m0 + wm * 64 + mt * 16 + gr;
#pragma unroll
        for (int nt = 0; nt < 4; nt++) {
            int col = n0 + wn * 32 + nt * 8 + gt * 2;
            float b0 = bias[col], b1 = bias[col + 1];
            float2 v0 = {acc[mt][nt][0] + b0, acc[mt][nt][1] + b1};
            float2 v1 = {acc[mt][nt][2] + b0, acc[mt][nt][3] + b1};
            if (relu) {
                v0.x = fmaxf(v0.x, 0.f); v0.y = fmaxf(v0.y, 0.f);
                v1.x = fmaxf(v1.x, 0.f); v1.y = fmaxf(v1.y, 0.f);
            }
            *(float2*)(C + (size_t)row * N + col)       = v0;
            *(float2*)(C + (size_t)(row + 8) * N + col) = v1;
        }
    }
}

// ---------------------------------------------------------------------------
// Streaming-softmax attention, fp32 (unchanged, known-correct).
// Reads projections with the reference's no-transpose reshape folded in.
// ---------------------------------------------------------------------------
#define AT_BM 64
#define AT_BN 32
#define NEG_BIG (-1e30f)

__device__ __forceinline__ size_t head_src_off(int b, int h, int s)
{
    return ((size_t)(b * SS + 128 * h + (s >> 4))) * D_MODEL
         + (size_t)(s & 15) * HD;
}

__global__ __launch_bounds__(256)
void attn_kernel(const float* __restrict__ Q, const float* __restrict__ K,
                 const float* __restrict__ V, float* __restrict__ Y, int causal)
{
    __shared__ float Qs[AT_BM][HD + 1];
    __shared__ float Ks[AT_BN][HD + 1];
    __shared__ float Vs[AT_BN][HD + 1];
    __shared__ float Ps[AT_BM][AT_BN];

    const int tid = threadIdx.x;
    const int tx = tid & 15;
    const int ty = tid >> 4;
    const int bh = blockIdx.y;
    const int h  = bh & (HEADS - 1);
    const int b  = bh >> 4;
    const int q0 = blockIdx.x * AT_BM;

    for (int i = tid; i < AT_BM * 16; i += 256) {
        int r = i >> 4, d4 = (i & 15);
        float4 t = ((const float4*)(Q + head_src_off(b, h, q0 + r)))[d4];
        Qs[r][d4 * 4 + 0] = t.x; Qs[r][d4 * 4 + 1] = t.y;
        Qs[r][d4 * 4 + 2] = t.z; Qs[r][d4 * 4 + 3] = t.w;
    }

    float m[4], l[4], o[4][4];
#pragma unroll
    for (int i = 0; i < 4; i++) {
        m[i] = NEG_BIG; l[i] = 0.f;
#pragma unroll
        for (int j = 0; j < 4; j++) o[i][j] = 0.f;
    }

    const int ntiles = causal ? (q0 / AT_BN + AT_BM / AT_BN) : (SS / AT_BN);
    for (int t = 0; t < ntiles; t++) {
        const int kv0 = t * AT_BN;
        __syncthreads();
        for (int i = tid; i < AT_BN * 16; i += 256) {
            int r = i >> 4, d4 = (i & 15);
            size_t so = head_src_off(b, h, kv0 + r);
            float4 tk = ((const float4*)(K + so))[d4];
            float4 tv = ((const float4*)(V + so))[d4];
            Ks[r][d4 * 4 + 0] = tk.x; Ks[r][d4 * 4 + 1] = tk.y;
            Ks[r][d4 * 4 + 2] = tk.z; Ks[r][d4 * 4 + 3] = tk.w;
            Vs[r][d4 * 4 + 0] = tv.x; Vs[r][d4 * 4 + 1] = tv.y;
            Vs[r][d4 * 4 + 2] = tv.z; Vs[r][d4 * 4 + 3] = tv.w;
        }
        __syncthreads();

        float sv[4][2];
#pragma unroll
        for (int i = 0; i < 4; i++) { sv[i][0] = 0.f; sv[i][1] = 0.f; }
#pragma unroll 8
        for (int d = 0; d < HD; d++) {
            float k0v = Ks[tx][d];
            float k1v = Ks[tx + 16][d];
#pragma unroll
            for (int i = 0; i < 4; i++) {
                float qv = Qs[ty * 4 + i][d];
                sv[i][0] = fmaf(qv, k0v, sv[i][0]);
                sv[i][1] = fmaf(qv, k1v, sv[i][1]);
            }
        }

#pragma unroll
        for (int i = 0; i < 4; i++) {
            const int qg = q0 + ty * 4 + i;
#pragma unroll
            for (int j = 0; j < 2; j++) {
                int kg = kv0 + tx + j * 16;
                float s = sv[i][j] * 0.125f;
                if (causal && kg > qg) s = NEG_BIG;
                sv[i][j] = s;
            }
            float rmax = fmaxf(sv[i][0], sv[i][1]);
#pragma unroll
            for (int off = 8; off > 0; off >>= 1)
                rmax = fmaxf(rmax, __shfl_xor_sync(0xffffffffu, rmax, off));
            float mnew = fmaxf(m[i], rmax);
            float sc = __expf(m[i] - mnew);
            float p0 = __expf(sv[i][0] - mnew);
            float p1 = __expf(sv[i][1] - mnew);
            float rsum = p0 + p1;
#pragma unroll
            for (int off = 8; off > 0; off >>= 1)
                rsum += __shfl_xor_sync(0xffffffffu, rsum, off);
            l[i] = l[i] * sc + rsum;
            m[i] = mnew;
#pragma unroll
            for (int j = 0; j < 4; j++) o[i][j] *= sc;
            Ps[ty * 4 + i][tx]      = p0;
            Ps[ty * 4 + i][tx + 16] = p1;
        }
        __syncthreads();

#pragma unroll 4
        for (int kk = 0; kk < AT_BN; kk++) {
            float vb[4];
#pragma unroll
            for (int j = 0; j < 4; j++) vb[j] = Vs[kk][tx + j * 16];
#pragma unroll
            for (int i = 0; i < 4; i++) {
                float pv = Ps[ty * 4 + i][kk];
#pragma unroll
                for (int j = 0; j < 4; j++)
                    o[i][j] = fmaf(pv, vb[j], o[i][j]);
            }
        }
    }

    float* Yp = Y + (size_t)b * SS * D_MODEL + (size_t)h * HD;
#pragma unroll
    for (int i = 0; i < 4; i++) {
        float inv = 1.f / l[i];
        size_t rb = (size_t)(q0 + ty * 4 + i) * D_MODEL;
#pragma unroll
        for (int j = 0; j < 4; j++)
            Yp[rb + tx + j * 16] = o[i][j] * inv;
    }
}

// ---------------------------------------------------------------------------
// Fused residual-add + LayerNorm over last dim (1024). One CTA per row.
// ---------------------------------------------------------------------------
__global__ __launch_bounds__(256)
void add_ln_kernel(const float* __restrict__ X, const float* __restrict__ Hh,
                   const float* __restrict__ g, const float* __restrict__ be,
                   float* __restrict__ Yo)
{
    const int row = blockIdx.x;
    const size_t base = (size_t)row * D_MODEL;
    const int tid = threadIdx.x;

    float v[4];
    float s = 0.f, s2 = 0.f;
#pragma unroll
    for (int u = 0; u < 4; u++) {
        int c = tid + u * 256;
        float t = X[base + c] + Hh[base + c];
        v[u] = t; s += t; s2 += t * t;
    }
#pragma unroll
    for (int off = 16; off > 0; off >>= 1) {
        s  += __shfl_down_sync(0xffffffffu, s,  off);
        s2 += __shfl_down_sync(0xffffffffu, s2, off);
    }
    __shared__ float rs_[8], rs2_[8];
    if ((tid & 31) == 0) { rs_[tid >> 5] = s; rs2_[tid >> 5] = s2; }
    __syncthreads();
    float ts = 0.f, ts2 = 0.f;
#pragma unroll
    for (int w = 0; w < 8; w++) { ts += rs_[w]; ts2 += rs2_[w]; }

    float mu   = ts * (1.0f / D_MODEL);
    float var  = ts2 * (1.0f / D_MODEL) - mu * mu;
    float rstd = rsqrtf(var + 1e-5f);
#pragma unroll
    for (int u = 0; u < 4; u++) {
        int c = tid + u * 256;
        Yo[base + c] = (v[u] - mu) * rstd * g[c] + be[c];
    }
}

// ---------------------------------------------------------------------------
// kernel_launch
// ---------------------------------------------------------------------------
extern "C" void kernel_launch(void* const* d_in, const int* in_sizes, int n_in,
                              void* d_out, int out_size)
{
    (void)in_sizes; (void)n_in; (void)out_size;

    const float* x    = (const float*)d_in[0];
    const float* enc  = (const float*)d_in[1];
    const float* s_wq = (const float*)d_in[2];  const float* s_bq = (const float*)d_in[3];
    const float* s_wk = (const float*)d_in[4];  const float* s_bk = (const float*)d_in[5];
    const float* s_wv = (const float*)d_in[6];  const float* s_bv = (const float*)d_in[7];
    const float* s_wo = (const float*)d_in[8];  const float* s_bo = (const float*)d_in[9];
    const float* c_wq = (const float*)d_in[10]; const float* c_bq = (const float*)d_in[11];
    const float* c_wk = (const float*)d_in[12]; const float* c_bk = (const float*)d_in[13];
    const float* c_wv = (const float*)d_in[14]; const float* c_bv = (const float*)d_in[15];
    const float* c_wo = (const float*)d_in[16]; const float* c_bo = (const float*)d_in[17];
    const float* f_w1 = (const float*)d_in[18]; const float* f_b1 = (const float*)d_in[19];
    const float* f_w2 = (const float*)d_in[20]; const float* f_b2 = (const float*)d_in[21];
    const float* ln1g = (const float*)d_in[22]; const float* ln1b = (const float*)d_in[23];
    const float* ln2g = (const float*)d_in[24]; const float* ln2b = (const float*)d_in[25];
    const float* ln3g = (const float*)d_in[26]; const float* ln3b = (const float*)d_in[27];
    float* out = (float*)d_out;

    float *q, *k, *v, *attn, *hb, *y1, *y2, *ff;
    __nv_bfloat16 *ah, *al, *wh, *wl;
    cudaGetSymbolAddress((void**)&q,    g_q);
    cudaGetSymbolAddress((void**)&k,    g_k);
    cudaGetSymbolAddress((void**)&v,    g_v);
    cudaGetSymbolAddress((void**)&attn, g_attn);
    cudaGetSymbolAddress((void**)&hb,   g_h);
    cudaGetSymbolAddress((void**)&y1,   g_y1);
    cudaGetSymbolAddress((void**)&y2,   g_y2);
    cudaGetSymbolAddress((void**)&ff,   g_ff);
    cudaGetSymbolAddress((void**)&ah,   g_ah);
    cudaGetSymbolAddress((void**)&al,   g_al);
    cudaGetSymbolAddress((void**)&wh,   g_wh);
    cudaGetSymbolAddress((void**)&wl,   g_wl);

    cudaFuncSetAttribute(gemm_bf16x3, cudaFuncAttributeMaxDynamicSharedMemorySize, GEMM_SMEM);

    const dim3 thr(256);
    const dim3 gAttn(SS / AT_BM, BH);
    const dim3 gLN(MTOK);
    const int n1  = MTOK * D_MODEL;        // 4M
    const int nff = MTOK * D_FF;           // 16M

#define SPLIT(src, n)   split_kernel<<<(n)/4/256, thr>>>((src), ah, al, (n)/4)
#define SPLITW(Wp, Kd, Nd) splitT_kernel<<<dim3((Nd)/32, (Kd)/32), thr>>>((Wp), wh, wl, (Kd), (Nd))
#define GEMM(bias, Cp, N_, K_, relu_) \
    gemm_bf16x3<<<dim3((N_)/128, MTOK/128), thr, GEMM_SMEM>>>(ah, al, wh, wl, (bias), (Cp), MTOK, (N_), (K_), (relu_))

    // ---- masked self-attention ----
    SPLIT(x, n1);
    SPLITW(s_wq, D_MODEL, D_MODEL); GEMM(s_bq, q, D_MODEL, D_MODEL, 0);
    SPLITW(s_wk, D_MODEL, D_MODEL); GEMM(s_bk, k, D_MODEL, D_MODEL, 0);
    SPLITW(s_wv, D_MODEL, D_MODEL); GEMM(s_bv, v, D_MODEL, D_MODEL, 0);
    attn_kernel<<<gAttn, thr>>>(q, k, v, attn, 1);
    SPLIT(attn, n1);
    SPLITW(s_wo, D_MODEL, D_MODEL); GEMM(s_bo, hb, D_MODEL, D_MODEL, 0);
    add_ln_kernel<<<gLN, thr>>>(x, hb, ln1g, ln1b, y1);

    // ---- cross-attention ----
    SPLIT(y1, n1);
    SPLITW(c_wq, D_MODEL, D_MODEL); GEMM(c_bq, q, D_MODEL, D_MODEL, 0);
    SPLIT(enc, n1);
    SPLITW(c_wk, D_MODEL, D_MODEL); GEMM(c_bk, k, D_MODEL, D_MODEL, 0);
    SPLITW(c_wv, D_MODEL, D_MODEL); GEMM(c_bv, v, D_MODEL, D_MODEL, 0);
    attn_kernel<<<gAttn, thr>>>(q, k, v, attn, 0);
    SPLIT(attn, n1);
    SPLITW(c_wo, D_MODEL, D_MODEL); GEMM(c_bo, hb, D_MODEL, D_MODEL, 0);
    add_ln_kernel<<<gLN, thr>>>(y1, hb, ln2g, ln2b, y2);

    // ---- FFN ----
    SPLIT(y2, n1);
    SPLITW(f_w1, D_MODEL, D_FF); GEMM(f_b1, ff, D_FF, D_MODEL, 1);
    SPLIT(ff, nff);
    SPLITW(f_w2, D_FF, D_MODEL); GEMM(f_b2, hb, D_MODEL, D_FF, 0);
    add_ln_kernel<<<gLN, thr>>>(y2, hb, ln3g, ln3b, out);

#undef SPLIT
#undef SPLITW
#undef GEMM
}

// round 6
// speedup vs baseline: 2.4551x; 1.5470x over previous
#include <cuda_runtime.h>
#include <cuda_bf16.h>
#include <math.h>
#include <stdint.h>

#define D_MODEL 1024
#define D_FF    4096
#define HEADS   16
#define HD      64
#define BB      2
#define SS      2048
#define MTOK    (BB*SS)      /* 4096 rows */
#define BH      (BB*HEADS)   /* 32 */

typedef __nv_bfloat16 bf16;

// ---------------------------------------------------------------------------
// Scratch (device globals; allocations are forbidden)
// ---------------------------------------------------------------------------
__device__ __align__(16) float g_hb [MTOK*(size_t)D_MODEL];
__device__ __align__(16) float g_y1 [MTOK*(size_t)D_MODEL];
__device__ __align__(16) float g_y2 [MTOK*(size_t)D_MODEL];
__device__ __align__(16) bf16 g_xh[MTOK*(size_t)D_MODEL];
__device__ __align__(16) bf16 g_xl[MTOK*(size_t)D_MODEL];
__device__ __align__(16) bf16 g_eh[MTOK*(size_t)D_MODEL];
__device__ __align__(16) bf16 g_el[MTOK*(size_t)D_MODEL];
__device__ __align__(16) bf16 g_qh[MTOK*(size_t)D_MODEL];
__device__ __align__(16) bf16 g_ql[MTOK*(size_t)D_MODEL];
__device__ __align__(16) bf16 g_kh[MTOK*(size_t)D_MODEL];
__device__ __align__(16) bf16 g_kl[MTOK*(size_t)D_MODEL];
__device__ __align__(16) bf16 g_vh[MTOK*(size_t)D_MODEL];
__device__ __align__(16) bf16 g_vl[MTOK*(size_t)D_MODEL];
__device__ __align__(16) bf16 g_oh[MTOK*(size_t)D_MODEL];
__device__ __align__(16) bf16 g_ol[MTOK*(size_t)D_MODEL];
__device__ __align__(16) bf16 g_y1h[MTOK*(size_t)D_MODEL];
__device__ __align__(16) bf16 g_y1l[MTOK*(size_t)D_MODEL];
__device__ __align__(16) bf16 g_y2h[MTOK*(size_t)D_MODEL];
__device__ __align__(16) bf16 g_y2l[MTOK*(size_t)D_MODEL];
__device__ __align__(16) bf16 g_fh[MTOK*(size_t)D_FF];
__device__ __align__(16) bf16 g_fl[MTOK*(size_t)D_FF];
__device__ __align__(16) bf16 g_wh[(size_t)D_FF*D_MODEL];
__device__ __align__(16) bf16 g_wl[(size_t)D_FF*D_MODEL];

// ---------------------------------------------------------------------------
// Small helpers
// ---------------------------------------------------------------------------
__device__ __forceinline__ void mma16816(float* d, const uint32_t* a, uint32_t b0, uint32_t b1)
{
    asm volatile(
        "mma.sync.aligned.m16n8k16.row.col.f32.bf16.bf16.f32 "
        "{%0,%1,%2,%3}, {%4,%5,%6,%7}, {%8,%9}, {%0,%1,%2,%3};"
        : "+f"(d[0]), "+f"(d[1]), "+f"(d[2]), "+f"(d[3])
        : "r"(a[0]), "r"(a[1]), "r"(a[2]), "r"(a[3]), "r"(b0), "r"(b1));
}
__device__ __forceinline__ void cp16(void* sdst, const void* gsrc)
{
    uint32_t d;
    asm("{ .reg .u64 t; cvta.to.shared.u64 t, %1; cvt.u32.u64 %0, t; }" : "=r"(d) : "l"(sdst));
    asm volatile("cp.async.cg.shared.global [%0], [%1], 16;\n" :: "r"(d), "l"(gsrc));
}
__device__ __forceinline__ uint32_t pack_hi(float a, float b)
{
    __nv_bfloat162 t = __floats2bfloat162_rn(a, b);
    return *reinterpret_cast<uint32_t*>(&t);
}
__device__ __forceinline__ uint32_t pack_lo(float a, float b)
{
    float ra = a - __bfloat162float(__float2bfloat16(a));
    float rb = b - __bfloat162float(__float2bfloat16(b));
    __nv_bfloat162 t = __floats2bfloat162_rn(ra, rb);
    return *reinterpret_cast<uint32_t*>(&t);
}

// ---------------------------------------------------------------------------
// fp32 -> bf16 hi/lo split (elementwise), n4 = n/4  (inputs x, enc only)
// ---------------------------------------------------------------------------
__global__ __launch_bounds__(256)
void split_kernel(const float* __restrict__ in, bf16* __restrict__ hi,
                  bf16* __restrict__ lo, int n4)
{
    int i = blockIdx.x * 256 + threadIdx.x;
    if (i >= n4) return;
    float4 f = ((const float4*)in)[i];
    float fv[4] = {f.x, f.y, f.z, f.w};
#pragma unroll
    for (int c = 0; c < 4; c++) {
        bf16 h = __float2bfloat16(fv[c]);
        bf16 l = __float2bfloat16(fv[c] - __bfloat162float(h));
        hi[(size_t)i * 4 + c] = h;
        lo[(size_t)i * 4 + c] = l;
    }
}

// ---------------------------------------------------------------------------
// W[K][N] fp32 -> Wt_hi/Wt_lo [N][K] bf16 (tiled transpose + split)
// ---------------------------------------------------------------------------
__global__ __launch_bounds__(256)
void splitT_kernel(const float* __restrict__ W, bf16* __restrict__ hi,
                   bf16* __restrict__ lo, int Kd, int Nd)
{
    __shared__ float t[32][33];
    int n0 = blockIdx.x * 32, k0 = blockIdx.y * 32;
    int tx = threadIdx.x & 31, ty = threadIdx.x >> 5;
#pragma unroll
    for (int r = ty; r < 32; r += 8)
        t[r][tx] = W[(size_t)(k0 + r) * Nd + n0 + tx];
    __syncthreads();
#pragma unroll
    for (int r = ty; r < 32; r += 8) {
        float f = t[tx][r];
        bf16 h = __float2bfloat16(f);
        bf16 l = __float2bfloat16(f - __bfloat162float(h));
        size_t o = (size_t)(n0 + r) * Kd + k0 + tx;
        hi[o] = h; lo[o] = l;
    }
}

// ---------------------------------------------------------------------------
// bf16x3 GEMM via mma.sync (m16n8k16), C = A @ W + bias (opt ReLU)
// mode 0: write fp32 C.  mode 1: write bf16 hi/lo (Chi/Clo).
// ---------------------------------------------------------------------------
#define GBK     32
#define SSTRIDE 40
#define TILEB   (128 * SSTRIDE * 2)
#define BUFB    (4 * TILEB)
#define GEMM_SMEM (2 * BUFB)

__device__ __forceinline__ void load_stage(char* buf,
        const bf16* pAh, const bf16* pAl,
        const bf16* pBh, const bf16* pBl,
        int K, int k0, int tid)
{
    const bf16* srcs[4] = {pAh, pAl, pBh, pBl};
#pragma unroll
    for (int t = 0; t < 4; t++) {
        char* tb = buf + t * TILEB;
        const bf16* g = srcs[t] + k0;
#pragma unroll
        for (int u = 0; u < 2; u++) {
            int id = tid + u * 256;
            int r = id >> 2, c = id & 3;
            cp16(tb + r * (SSTRIDE * 2) + c * 16, g + (size_t)r * K + c * 8);
        }
    }
}

__global__ __launch_bounds__(256)
void gemm_bf16x3(const bf16* __restrict__ Ahi, const bf16* __restrict__ Alo,
                 const bf16* __restrict__ Bhi, const bf16* __restrict__ Blo,
                 const float* __restrict__ bias, float* __restrict__ C,
                 bf16* __restrict__ Chi, bf16* __restrict__ Clo,
                 int M, int N, int K, int relu, int mode)
{
    extern __shared__ char smem[];

    const int tid = threadIdx.x;
    const int wid = tid >> 5;
    const int lid = tid & 31;
    const int wm  = wid >> 2;
    const int wn  = wid & 3;
    const int m0  = blockIdx.y * 128;
    const int n0  = blockIdx.x * 128;

    const bf16* pAh = Ahi + (size_t)m0 * K;
    const bf16* pAl = Alo + (size_t)m0 * K;
    const bf16* pBh = Bhi + (size_t)n0 * K;
    const bf16* pBl = Blo + (size_t)n0 * K;

    float acc[4][4][4];
#pragma unroll
    for (int i = 0; i < 4; i++)
#pragma unroll
        for (int j = 0; j < 4; j++)
#pragma unroll
            for (int c = 0; c < 4; c++) acc[i][j][c] = 0.f;

    const int gr = lid >> 2;
    const int gt = lid & 3;
    const int aRow0 = wm * 64 + gr;
    const int bRow0 = wn * 32 + gr;
    const int nst = K / GBK;

    load_stage(smem, pAh, pAl, pBh, pBl, K, 0, tid);
    asm volatile("cp.async.commit_group;\n" ::: "memory");

    for (int s = 0; s < nst; s++) {
        if (s + 1 < nst) {
            load_stage(smem + ((s + 1) & 1) * BUFB, pAh, pAl, pBh, pBl,
                       K, (s + 1) * GBK, tid);
            asm volatile("cp.async.commit_group;\n" ::: "memory");
            asm volatile("cp.async.wait_group 1;\n" ::: "memory");
        } else {
            asm volatile("cp.async.wait_group 0;\n" ::: "memory");
        }
        __syncthreads();

        char* buf = smem + (s & 1) * BUFB;
        char* tAh = buf;
        char* tAl = buf + TILEB;
        char* tBh = buf + 2 * TILEB;
        char* tBl = buf + 3 * TILEB;

#pragma unroll
        for (int ks = 0; ks < 2; ks++) {
            const int kb = ks * 32 + gt * 4;
            uint32_t ah[4][4], al[4][4], bh[4][2], bl[4][2];
#pragma unroll
            for (int mt = 0; mt < 4; mt++) {
                int r0 = (aRow0 + mt * 16) * (SSTRIDE * 2);
                int r8 = r0 + 8 * (SSTRIDE * 2);
                ah[mt][0] = *(uint32_t*)(tAh + r0 + kb);
                ah[mt][1] = *(uint32_t*)(tAh + r8 + kb);
                ah[mt][2] = *(uint32_t*)(tAh + r0 + kb + 16);
                ah[mt][3] = *(uint32_t*)(tAh + r8 + kb + 16);
                al[mt][0] = *(uint32_t*)(tAl + r0 + kb);
                al[mt][1] = *(uint32_t*)(tAl + r8 + kb);
                al[mt][2] = *(uint32_t*)(tAl + r0 + kb + 16);
                al[mt][3] = *(uint32_t*)(tAl + r8 + kb + 16);
            }
#pragma unroll
            for (int nt = 0; nt < 4; nt++) {
                int r = (bRow0 + nt * 8) * (SSTRIDE * 2);
                bh[nt][0] = *(uint32_t*)(tBh + r + kb);
                bh[nt][1] = *(uint32_t*)(tBh + r + kb + 16);
                bl[nt][0] = *(uint32_t*)(tBl + r + kb);
                bl[nt][1] = *(uint32_t*)(tBl + r + kb + 16);
            }
#pragma unroll
            for (int mt = 0; mt < 4; mt++)
#pragma unroll
                for (int nt = 0; nt < 4; nt++) {
                    mma16816(acc[mt][nt], ah[mt], bh[nt][0], bh[nt][1]);
                    mma16816(acc[mt][nt], ah[mt], bl[nt][0], bl[nt][1]);
                    mma16816(acc[mt][nt], al[mt], bh[nt][0], bh[nt][1]);
                }
        }
        __syncthreads();
    }

#pragma unroll
    for (int mt = 0; mt < 4; mt++) {
        int row = m0 + wm * 64 + mt * 16 + gr;
#pragma unroll
        for (int nt = 0; nt < 4; nt++) {
            int col = n0 + wn * 32 + nt * 8 + gt * 2;
            float b0 = bias[col], b1 = bias[col + 1];
            float v0 = acc[mt][nt][0] + b0, v1 = acc[mt][nt][1] + b1;
            float v2 = acc[mt][nt][2] + b0, v3 = acc[mt][nt][3] + b1;
            if (relu) {
                v0 = fmaxf(v0, 0.f); v1 = fmaxf(v1, 0.f);
                v2 = fmaxf(v2, 0.f); v3 = fmaxf(v3, 0.f);
            }
            if (mode == 0) {
                *(float2*)(C + (size_t)row * N + col)       = make_float2(v0, v1);
                *(float2*)(C + (size_t)(row + 8) * N + col) = make_float2(v2, v3);
            } else {
                *(uint32_t*)(Chi + (size_t)row * N + col)       = pack_hi(v0, v1);
                *(uint32_t*)(Clo + (size_t)row * N + col)       = pack_lo(v0, v1);
                *(uint32_t*)(Chi + (size_t)(row + 8) * N + col) = pack_hi(v2, v3);
                *(uint32_t*)(Clo + (size_t)(row + 8) * N + col) = pack_lo(v2, v3);
            }
        }
    }
}

// ---------------------------------------------------------------------------
// Tensor-core flash attention, bf16x3 numerics.
// Q/K/V given as hi/lo bf16 in projection layout [4096][1024] with the
// reference's no-transpose reshape folded into the gather:
//   head h, seq s -> row (b*SS + 128h + s/16), cols [64*(s%16), +64)
// Output written as bf16 hi/lo in merged-heads layout [b*SS+s][h*64+d].
// CTA: 128 q rows, 8 warps (16 rows each), KV tiles of 64, double-buffered.
// ---------------------------------------------------------------------------
#define FBM 128
#define FBN 64
#define FSTR 72
#define ATT_SMEM 73728

__device__ __forceinline__ size_t head_src_off(int b, int h, int s)
{
    return ((size_t)(b * SS + 128 * h + (s >> 4))) * D_MODEL
         + (size_t)(s & 15) * HD;
}

__device__ __forceinline__ void attn_ldkv(bf16* base,
    const bf16* Kh_g, const bf16* Kl_g, const bf16* Vh_g, const bf16* Vl_g,
    int b, int h, int kv0, int tid)
{
    for (int i = tid; i < 512; i += 256) {
        int r = i >> 3, c = (i & 7) * 8;
        size_t so = head_src_off(b, h, kv0 + r) + c;
        int e = r * FSTR + c;
        cp16(base + e,         Kh_g + so);
        cp16(base + 4608 + e,  Kl_g + so);
        cp16(base + 9216 + e,  Vh_g + so);
        cp16(base + 13824 + e, Vl_g + so);
    }
}

__global__ __launch_bounds__(256)
void attn_mma_kernel(const bf16* __restrict__ Qh_g, const bf16* __restrict__ Ql_g,
                     const bf16* __restrict__ Kh_g, const bf16* __restrict__ Kl_g,
                     const bf16* __restrict__ Vh_g, const bf16* __restrict__ Vl_g,
                     bf16* __restrict__ Oh_g, bf16* __restrict__ Ol_g, int causal)
{
    extern __shared__ __align__(16) char smraw[];
    bf16* smb = (bf16*)smraw;

    const int tid = threadIdx.x;
    const int wid = tid >> 5;
    const int lid = tid & 31;
    const int gr = lid >> 2, gt = lid & 3;
    const int bh = blockIdx.y, h = bh & 15, b = bh >> 4;
    const int q0 = blockIdx.x * FBM;

    // ---- stage Q (hi: elems 0..9215, lo: 9216..18431) ----
    bf16* sQh = smb;
    bf16* sQl = smb + 9216;
    for (int i = tid; i < 1024; i += 256) {
        int r = i >> 3, c = (i & 7) * 8;
        size_t so = head_src_off(b, h, q0 + r) + c;
        *(uint4*)(sQh + r * FSTR + c) = *(const uint4*)(Qh_g + so);
        *(uint4*)(sQl + r * FSTR + c) = *(const uint4*)(Ql_g + so);
    }
    __syncthreads();

    uint32_t qh[4][4], ql[4][4];
    {
        int rb = (wid * 16 + gr) * FSTR;
#pragma unroll
        for (int kt = 0; kt < 4; kt++) {
            int e = rb + kt * 16 + gt * 2;
            qh[kt][0] = *(uint32_t*)(sQh + e);
            qh[kt][1] = *(uint32_t*)(sQh + e + 8 * FSTR);
            qh[kt][2] = *(uint32_t*)(sQh + e + 8);
            qh[kt][3] = *(uint32_t*)(sQh + e + 8 * FSTR + 8);
            ql[kt][0] = *(uint32_t*)(sQl + e);
            ql[kt][1] = *(uint32_t*)(sQl + e + 8 * FSTR);
            ql[kt][2] = *(uint32_t*)(sQl + e + 8);
            ql[kt][3] = *(uint32_t*)(sQl + e + 8 * FSTR + 8);
        }
    }
    __syncthreads();

    float m0 = -1e30f, m1 = -1e30f, l0 = 0.f, l1 = 0.f;
    float o[8][4];
#pragma unroll
    for (int nt = 0; nt < 8; nt++)
#pragma unroll
        for (int c = 0; c < 4; c++) o[nt][c] = 0.f;

    const int r0g = q0 + wid * 16 + gr;
    const int ntiles = causal ? (q0 / FBN + FBM / FBN) : (SS / FBN);

    attn_ldkv(smb, Kh_g, Kl_g, Vh_g, Vl_g, b, h, 0, tid);
    asm volatile("cp.async.commit_group;\n" ::: "memory");

    for (int t = 0; t < ntiles; t++) {
        if (t + 1 < ntiles) {
            attn_ldkv(smb + ((t + 1) & 1) * 18432, Kh_g, Kl_g, Vh_g, Vl_g,
                      b, h, (t + 1) * FBN, tid);
            asm volatile("cp.async.commit_group;\n" ::: "memory");
            asm volatile("cp.async.wait_group 1;\n" ::: "memory");
        } else {
            asm volatile("cp.async.wait_group 0;\n" ::: "memory");
        }
        __syncthreads();

        const bf16* kb  = smb + (t & 1) * 18432;
        const bf16* sKh = kb;
        const bf16* sKl = kb + 4608;
        const bf16* sVh = kb + 9216;
        const bf16* sVl = kb + 13824;
        const int kv0 = t * FBN;

        // ---- S = Q K^T (3-pass) ----
        float s[8][4];
#pragma unroll
        for (int nt = 0; nt < 8; nt++)
#pragma unroll
            for (int c = 0; c < 4; c++) s[nt][c] = 0.f;

#pragma unroll
        for (int nt = 0; nt < 8; nt++) {
            int krow = (nt * 8 + gr) * FSTR;
#pragma unroll
            for (int kt = 0; kt < 4; kt++) {
                int e = krow + kt * 16 + gt * 2;
                uint32_t b0 = *(const uint32_t*)(sKh + e);
                uint32_t b1 = *(const uint32_t*)(sKh + e + 8);
                uint32_t c0 = *(const uint32_t*)(sKl + e);
                uint32_t c1 = *(const uint32_t*)(sKl + e + 8);
                mma16816(s[nt], qh[kt], b0, b1);
                mma16816(s[nt], qh[kt], c0, c1);
                mma16816(s[nt], ql[kt], b0, b1);
            }
        }

        // ---- online softmax ----
        const bool needm = causal && (kv0 + FBN - 1 > r0g);
        float rm0 = -1e30f, rm1 = -1e30f;
#pragma unroll
        for (int nt = 0; nt < 8; nt++) {
#pragma unroll
            for (int c = 0; c < 4; c++) {
                float v = s[nt][c] * 0.125f;
                if (needm) {
                    int col = kv0 + nt * 8 + gt * 2 + (c & 1);
                    int row = (c < 2) ? r0g : (r0g + 8);
                    if (col > row) v = -1e30f;
                }
                s[nt][c] = v;
            }
            rm0 = fmaxf(rm0, fmaxf(s[nt][0], s[nt][1]));
            rm1 = fmaxf(rm1, fmaxf(s[nt][2], s[nt][3]));
        }
        rm0 = fmaxf(rm0, __shfl_xor_sync(0xffffffffu, rm0, 1));
        rm0 = fmaxf(rm0, __shfl_xor_sync(0xffffffffu, rm0, 2));
        rm1 = fmaxf(rm1, __shfl_xor_sync(0xffffffffu, rm1, 1));
        rm1 = fmaxf(rm1, __shfl_xor_sync(0xffffffffu, rm1, 2));

        float mn0 = fmaxf(m0, rm0), mn1 = fmaxf(m1, rm1);
        float sc0 = __expf(m0 - mn0), sc1 = __expf(m1 - mn1);
        m0 = mn0; m1 = mn1;
        l0 *= sc0; l1 *= sc1;
#pragma unroll
        for (int nt = 0; nt < 8; nt++) {
            s[nt][0] = __expf(s[nt][0] - mn0); l0 += s[nt][0];
            s[nt][1] = __expf(s[nt][1] - mn0); l0 += s[nt][1];
            s[nt][2] = __expf(s[nt][2] - mn1); l1 += s[nt][2];
            s[nt][3] = __expf(s[nt][3] - mn1); l1 += s[nt][3];
            o[nt][0] *= sc0; o[nt][1] *= sc0;
            o[nt][2] *= sc1; o[nt][3] *= sc1;
        }

        // ---- O += P V (3-pass); P fragments straight from S registers ----
#pragma unroll
        for (int kt = 0; kt < 4; kt++) {
            uint32_t pah[4], pal[4];
            pah[0] = pack_hi(s[2*kt][0],   s[2*kt][1]);
            pah[1] = pack_hi(s[2*kt][2],   s[2*kt][3]);
            pah[2] = pack_hi(s[2*kt+1][0], s[2*kt+1][1]);
            pah[3] = pack_hi(s[2*kt+1][2], s[2*kt+1][3]);
            pal[0] = pack_lo(s[2*kt][0],   s[2*kt][1]);
            pal[1] = pack_lo(s[2*kt][2],   s[2*kt][3]);
            pal[2] = pack_lo(s[2*kt+1][0], s[2*kt+1][1]);
            pal[3] = pack_lo(s[2*kt+1][2], s[2*kt+1][3]);

            int kr = (kt * 16 + gt * 2) * FSTR;
#pragma unroll
            for (int nt = 0; nt < 8; nt++) {
                int vc = nt * 8 + gr;
                unsigned short w0 = *(const unsigned short*)(sVh + kr + vc);
                unsigned short w1 = *(const unsigned short*)(sVh + kr + FSTR + vc);
                unsigned short w2 = *(const unsigned short*)(sVh + kr + 8 * FSTR + vc);
                unsigned short w3 = *(const unsigned short*)(sVh + kr + 9 * FSTR + vc);
                uint32_t vb0 = (uint32_t)w0 | ((uint32_t)w1 << 16);
                uint32_t vb1 = (uint32_t)w2 | ((uint32_t)w3 << 16);
                unsigned short x0 = *(const unsigned short*)(sVl + kr + vc);
                unsigned short x1 = *(const unsigned short*)(sVl + kr + FSTR + vc);
                unsigned short x2 = *(const unsigned short*)(sVl + kr + 8 * FSTR + vc);
                unsigned short x3 = *(const unsigned short*)(sVl + kr + 9 * FSTR + vc);
                uint32_t vl0 = (uint32_t)x0 | ((uint32_t)x1 << 16);
                uint32_t vl1 = (uint32_t)x2 | ((uint32_t)x3 << 16);
                mma16816(o[nt], pah, vb0, vb1);
                mma16816(o[nt], pah, vl0, vl1);
                mma16816(o[nt], pal, vb0, vb1);
            }
        }
        __syncthreads();
    }

    // ---- finalize: row-sum across the 4 lanes sharing a row, normalize ----
    l0 += __shfl_xor_sync(0xffffffffu, l0, 1);
    l0 += __shfl_xor_sync(0xffffffffu, l0, 2);
    l1 += __shfl_xor_sync(0xffffffffu, l1, 1);
    l1 += __shfl_xor_sync(0xffffffffu, l1, 2);
    float inv0 = 1.f / l0, inv1 = 1.f / l1;

    size_t base0 = ((size_t)(b * SS) + r0g) * D_MODEL + h * 64;
    size_t base1 = base0 + 8 * (size_t)D_MODEL;
#pragma unroll
    for (int nt = 0; nt < 8; nt++) {
        int c = nt * 8 + gt * 2;
        float v0 = o[nt][0] * inv0, v1 = o[nt][1] * inv0;
        float w0 = o[nt][2] * inv1, w1 = o[nt][3] * inv1;
        *(uint32_t*)(Oh_g + base0 + c) = pack_hi(v0, v1);
        *(uint32_t*)(Ol_g + base0 + c) = pack_lo(v0, v1);
        *(uint32_t*)(Oh_g + base1 + c) = pack_hi(w0, w1);
        *(uint32_t*)(Ol_g + base1 + c) = pack_lo(w0, w1);
    }
}

// ---------------------------------------------------------------------------
// Fused residual-add + LayerNorm; optional bf16 hi/lo side outputs.
// ---------------------------------------------------------------------------
__global__ __launch_bounds__(256)
void add_ln_kernel(const float* __restrict__ X, const float* __restrict__ Hh,
                   const float* __restrict__ g, const float* __restrict__ be,
                   float* __restrict__ Yo, bf16* __restrict__ yh,
                   bf16* __restrict__ yl, int wantbf)
{
    const int row = blockIdx.x;
    const size_t base = (size_t)row * D_MODEL;
    const int tid = threadIdx.x;

    float v[4];
    float s = 0.f, s2 = 0.f;
#pragma unroll
    for (int u = 0; u < 4; u++) {
        int c = tid + u * 256;
        float t = X[base + c] + Hh[base + c];
        v[u] = t; s += t; s2 += t * t;
    }
#pragma unroll
    for (int off = 16; off > 0; off >>= 1) {
        s  += __shfl_down_sync(0xffffffffu, s,  off);
        s2 += __shfl_down_sync(0xffffffffu, s2, off);
    }
    __shared__ float rs_[8], rs2_[8];
    if ((tid & 31) == 0) { rs_[tid >> 5] = s; rs2_[tid >> 5] = s2; }
    __syncthreads();
    float ts = 0.f, ts2 = 0.f;
#pragma unroll
    for (int w = 0; w < 8; w++) { ts += rs_[w]; ts2 += rs2_[w]; }

    float mu   = ts * (1.0f / D_MODEL);
    float var  = ts2 * (1.0f / D_MODEL) - mu * mu;
    float rstd = rsqrtf(var + 1e-5f);
#pragma unroll
    for (int u = 0; u < 4; u++) {
        int c = tid + u * 256;
        float val = (v[u] - mu) * rstd * g[c] + be[c];
        Yo[base + c] = val;
        if (wantbf) {
            bf16 hh = __float2bfloat16(val);
            yh[base + c] = hh;
            yl[base + c] = __float2bfloat16(val - __bfloat162float(hh));
        }
    }
}

// ---------------------------------------------------------------------------
// kernel_launch
// ---------------------------------------------------------------------------
extern "C" void kernel_launch(void* const* d_in, const int* in_sizes, int n_in,
                              void* d_out, int out_size)
{
    (void)in_sizes; (void)n_in; (void)out_size;

    const float* x    = (const float*)d_in[0];
    const float* enc  = (const float*)d_in[1];
    const float* s_wq = (const float*)d_in[2];  const float* s_bq = (const float*)d_in[3];
    const float* s_wk = (const float*)d_in[4];  const float* s_bk = (const float*)d_in[5];
    const float* s_wv = (const float*)d_in[6];  const float* s_bv = (const float*)d_in[7];
    const float* s_wo = (const float*)d_in[8];  const float* s_bo = (const float*)d_in[9];
    const float* c_wq = (const float*)d_in[10]; const float* c_bq = (const float*)d_in[11];
    const float* c_wk = (const float*)d_in[12]; const float* c_bk = (const float*)d_in[13];
    const float* c_wv = (const float*)d_in[14]; const float* c_bv = (const float*)d_in[15];
    const float* c_wo = (const float*)d_in[16]; const float* c_bo = (const float*)d_in[17];
    const float* f_w1 = (const float*)d_in[18]; const float* f_b1 = (const float*)d_in[19];
    const float* f_w2 = (const float*)d_in[20]; const float* f_b2 = (const float*)d_in[21];
    const float* ln1g = (const float*)d_in[22]; const float* ln1b = (const float*)d_in[23];
    const float* ln2g = (const float*)d_in[24]; const float* ln2b = (const float*)d_in[25];
    const float* ln3g = (const float*)d_in[26]; const float* ln3b = (const float*)d_in[27];
    float* out = (float*)d_out;

    float *hb, *y1, *y2;
    bf16 *xh, *xl, *eh, *el, *qh, *ql, *kh, *kl, *vh, *vl, *oh, *ol;
    bf16 *y1h, *y1l, *y2h, *y2l, *fh, *fl, *wh, *wl;
    cudaGetSymbolAddress((void**)&hb,  g_hb);
    cudaGetSymbolAddress((void**)&y1,  g_y1);
    cudaGetSymbolAddress((void**)&y2,  g_y2);
    cudaGetSymbolAddress((void**)&xh,  g_xh);  cudaGetSymbolAddress((void**)&xl,  g_xl);
    cudaGetSymbolAddress((void**)&eh,  g_eh);  cudaGetSymbolAddress((void**)&el,  g_el);
    cudaGetSymbolAddress((void**)&qh,  g_qh);  cudaGetSymbolAddress((void**)&ql,  g_ql);
    cudaGetSymbolAddress((void**)&kh,  g_kh);  cudaGetSymbolAddress((void**)&kl,  g_kl);
    cudaGetSymbolAddress((void**)&vh,  g_vh);  cudaGetSymbolAddress((void**)&vl,  g_vl);
    cudaGetSymbolAddress((void**)&oh,  g_oh);  cudaGetSymbolAddress((void**)&ol,  g_ol);
    cudaGetSymbolAddress((void**)&y1h, g_y1h); cudaGetSymbolAddress((void**)&y1l, g_y1l);
    cudaGetSymbolAddress((void**)&y2h, g_y2h); cudaGetSymbolAddress((void**)&y2l, g_y2l);
    cudaGetSymbolAddress((void**)&fh,  g_fh);  cudaGetSymbolAddress((void**)&fl,  g_fl);
    cudaGetSymbolAddress((void**)&wh,  g_wh);  cudaGetSymbolAddress((void**)&wl,  g_wl);

    cudaFuncSetAttribute(gemm_bf16x3, cudaFuncAttributeMaxDynamicSharedMemorySize, GEMM_SMEM);
    cudaFuncSetAttribute(attn_mma_kernel, cudaFuncAttributeMaxDynamicSharedMemorySize, ATT_SMEM);

    const dim3 thr(256);
    const dim3 gAttn(SS / FBM, BH);              // (16, 32)
    const dim3 gLN(MTOK);
    const int n1 = MTOK * D_MODEL;

#define SPLITW(Wp, Kd, Nd) splitT_kernel<<<dim3((Nd)/32, (Kd)/32), thr>>>((Wp), wh, wl, (Kd), (Nd))
#define GEMMF(Ah, Al, bias, Cp, N_, K_, relu_) \
    gemm_bf16x3<<<dim3((N_)/128, MTOK/128), thr, GEMM_SMEM>>>((Ah), (Al), wh, wl, (bias), (Cp), 0, 0, MTOK, (N_), (K_), (relu_), 0)
#define GEMMB(Ah, Al, bias, Ch, Cl, N_, K_, relu_) \
    gemm_bf16x3<<<dim3((N_)/128, MTOK/128), thr, GEMM_SMEM>>>((Ah), (Al), wh, wl, (bias), 0, (Ch), (Cl), MTOK, (N_), (K_), (relu_), 1)

    // ---- masked self-attention ----
    split_kernel<<<n1 / 4 / 256, thr>>>(x, xh, xl, n1 / 4);
    SPLITW(s_wq, D_MODEL, D_MODEL); GEMMB(xh, xl, s_bq, qh, ql, D_MODEL, D_MODEL, 0);
    SPLITW(s_wk, D_MODEL, D_MODEL); GEMMB(xh, xl, s_bk, kh, kl, D_MODEL, D_MODEL, 0);
    SPLITW(s_wv, D_MODEL, D_MODEL); GEMMB(xh, xl, s_bv, vh, vl, D_MODEL, D_MODEL, 0);
    attn_mma_kernel<<<gAttn, thr, ATT_SMEM>>>(qh, ql, kh, kl, vh, vl, oh, ol, 1);
    SPLITW(s_wo, D_MODEL, D_MODEL); GEMMF(oh, ol, s_bo, hb, D_MODEL, D_MODEL, 0);
    add_ln_kernel<<<gLN, thr>>>(x, hb, ln1g, ln1b, y1, y1h, y1l, 1);

    // ---- cross-attention ----
    SPLITW(c_wq, D_MODEL, D_MODEL); GEMMB(y1h, y1l, c_bq, qh, ql, D_MODEL, D_MODEL, 0);
    split_kernel<<<n1 / 4 / 256, thr>>>(enc, eh, el, n1 / 4);
    SPLITW(c_wk, D_MODEL, D_MODEL); GEMMB(eh, el, c_bk, kh, kl, D_MODEL, D_MODEL, 0);
    SPLITW(c_wv, D_MODEL, D_MODEL); GEMMB(eh, el, c_bv, vh, vl, D_MODEL, D_MODEL, 0);
    attn_mma_kernel<<<gAttn, thr, ATT_SMEM>>>(qh, ql, kh, kl, vh, vl, oh, ol, 0);
    SPLITW(c_wo, D_MODEL, D_MODEL); GEMMF(oh, ol, c_bo, hb, D_MODEL, D_MODEL, 0);
    add_ln_kernel<<<gLN, thr>>>(y1, hb, ln2g, ln2b, y2, y2h, y2l, 1);

    // ---- FFN ----
    SPLITW(f_w1, D_MODEL, D_FF); GEMMB(y2h, y2l, f_b1, fh, fl, D_FF, D_MODEL, 1);
    SPLITW(f_w2, D_FF, D_MODEL); GEMMF(fh, fl, f_b2, hb, D_MODEL, D_FF, 0);
    add_ln_kernel<<<gLN, thr>>>(y2, hb, ln3g, ln3b, out, 0, 0, 0);

#undef SPLITW
#undef GEMMF
#undef GEMMB
}